// round 2
// baseline (speedup 1.0000x reference)
#include <cuda_runtime.h>
#include <cuda_bf16.h>
#include <math.h>

// Problem constants
#define BB 2
#define SS 4096
#define DD 256
#define HH 8
#define DHH 32
#define DMM 1024
#define MM (BB*SS)   // 8192

// ---------------- scratch (device globals, allocation-free) ----------------
__device__ float g_xn  [MM*DD];    // LN output / reused for LN2 output
__device__ float g_q   [MM*DD];
__device__ float g_k   [MM*DD];
__device__ float g_v   [MM*DD];
__device__ float g_attn[MM*DD];
__device__ float g_res [MM*DD];    // mlp_in = attn@Wo + x
__device__ float g_hid [MM*DMM];

// ---------------- LayerNorm: one block (256 threads) per row ----------------
__global__ void ln_kernel(const float* __restrict__ x,
                          const float* __restrict__ g,
                          const float* __restrict__ b,
                          float* __restrict__ out)
{
    int row = blockIdx.x;
    int tid = threadIdx.x;
    const float* xr = x + (size_t)row * DD;
    float v = xr[tid];
    float s = v, s2 = v * v;
    #pragma unroll
    for (int off = 16; off > 0; off >>= 1) {
        s  += __shfl_down_sync(0xffffffffu, s,  off);
        s2 += __shfl_down_sync(0xffffffffu, s2, off);
    }
    __shared__ float ws[8], ws2[8];
    __shared__ float s_mu, s_rstd;
    int wid = tid >> 5, lane = tid & 31;
    if (lane == 0) { ws[wid] = s; ws2[wid] = s2; }
    __syncthreads();
    if (tid == 0) {
        float ts = 0.f, ts2 = 0.f;
        #pragma unroll
        for (int i = 0; i < 8; i++) { ts += ws[i]; ts2 += ws2[i]; }
        float mu = ts * (1.0f / DD);
        float var = ts2 * (1.0f / DD) - mu * mu;
        s_mu = mu;
        s_rstd = rsqrtf(var + 1e-5f);
    }
    __syncthreads();
    out[(size_t)row * DD + tid] = (v - s_mu) * s_rstd * g[tid] + b[tid];
}

// ---------------- Generic SGEMM: C[M,N] = A[M,K] @ W[N,K]^T (+epilogue) ----
// EPI: 0 = none, 1 = bias + exact GELU, 2 = bias(optional) + residual add
template<int EPI>
__global__ void __launch_bounds__(256)
gemm_kernel(const float* __restrict__ A, const float* __restrict__ W,
            const float* __restrict__ bias, const float* __restrict__ res,
            float* __restrict__ C, int M, int N, int K)
{
    __shared__ float As[16][64];
    __shared__ float Bs[16][64];

    int t  = threadIdx.x;          // 0..255
    int tx = t & 15;               // col group
    int ty = t >> 4;               // row group
    int rm0 = blockIdx.y * 64;
    int cn0 = blockIdx.x * 64;

    int lrow = t >> 2;             // 0..63
    int lc4  = (t & 3) * 4;        // 0,4,8,12

    float acc[4][4];
    #pragma unroll
    for (int i = 0; i < 4; i++)
        #pragma unroll
        for (int j = 0; j < 4; j++) acc[i][j] = 0.f;

    for (int k0 = 0; k0 < K; k0 += 16) {
        float4 a4 = *(const float4*)(A + (size_t)(rm0 + lrow) * K + k0 + lc4);
        float4 w4 = *(const float4*)(W + (size_t)(cn0 + lrow) * K + k0 + lc4);
        As[lc4 + 0][lrow] = a4.x; As[lc4 + 1][lrow] = a4.y;
        As[lc4 + 2][lrow] = a4.z; As[lc4 + 3][lrow] = a4.w;
        Bs[lc4 + 0][lrow] = w4.x; Bs[lc4 + 1][lrow] = w4.y;
        Bs[lc4 + 2][lrow] = w4.z; Bs[lc4 + 3][lrow] = w4.w;
        __syncthreads();
        #pragma unroll
        for (int kk = 0; kk < 16; kk++) {
            float4 af = *(const float4*)(&As[kk][ty * 4]);
            float4 bf = *(const float4*)(&Bs[kk][tx * 4]);
            float a[4] = {af.x, af.y, af.z, af.w};
            float b[4] = {bf.x, bf.y, bf.z, bf.w};
            #pragma unroll
            for (int i = 0; i < 4; i++)
                #pragma unroll
                for (int j = 0; j < 4; j++)
                    acc[i][j] = fmaf(a[i], b[j], acc[i][j]);
        }
        __syncthreads();
    }

    #pragma unroll
    for (int i = 0; i < 4; i++) {
        int r = rm0 + ty * 4 + i;
        #pragma unroll
        for (int j = 0; j < 4; j++) {
            int c = cn0 + tx * 4 + j;
            float v = acc[i][j];
            if (EPI == 1) {
                v += bias[c];
                v = 0.5f * v * (1.0f + erff(v * 0.70710678118654752f));
            } else if (EPI == 2) {
                if (bias) v += bias[c];
                v += res[(size_t)r * N + c];
            }
            C[(size_t)r * N + c] = v;
        }
    }
}

// ---------------- RoPE on q and k (interleaved pairs) ----------------------
__global__ void rope_kernel(float* __restrict__ q, float* __restrict__ k)
{
    int idx = blockIdx.x * blockDim.x + threadIdx.x;   // over MM*HH*16 pairs
    if (idx >= MM * HH * (DHH / 2)) return;
    int i   = idx & 15;            // pair index 0..15
    int h   = (idx >> 4) & 7;
    int row = idx >> 7;            // 0..8191
    int pos = row & (SS - 1);

    // inv_freq = 10000^{-(2i)/32}
    float inv = __expf(-((float)(2 * i) / 32.0f) * 9.210340371976184f);
    float theta = (float)pos * inv;
    float sn, cs;
    sincosf(theta, &sn, &cs);

    size_t off = (size_t)row * DD + h * DHH + 2 * i;
    float q0 = q[off], q1 = q[off + 1];
    q[off]     = q0 * cs - q1 * sn;
    q[off + 1] = q1 * cs + q0 * sn;
    float k0 = k[off], k1 = k[off + 1];
    k[off]     = k0 * cs - k1 * sn;
    k[off + 1] = k1 * cs + k0 * sn;
}

// ---------------- Flash attention: 1 query row / thread --------------------
// grid = (S/128, H, B), block = 128
#define KT 128
#define KSTRIDE 36   // padding: kills 32-way STS bank conflict (8-way residual)
__global__ void __launch_bounds__(128)
attn_kernel(const float* __restrict__ q, const float* __restrict__ k,
            const float* __restrict__ v, float* __restrict__ o)
{
    __shared__ float Ks[KT][KSTRIDE];
    __shared__ float Vs[KT][KSTRIDE];

    int b  = blockIdx.z;
    int h  = blockIdx.y;
    int t  = threadIdx.x;
    int row = b * SS + blockIdx.x * 128 + t;

    const float scale = 0.1767766952966369f;  // 1/sqrt(32)
    float qr[DHH];
    {
        const float* qp = q + (size_t)row * DD + h * DHH;
        #pragma unroll
        for (int d = 0; d < DHH; d += 4) {
            float4 f = *(const float4*)(qp + d);
            qr[d] = f.x * scale; qr[d+1] = f.y * scale;
            qr[d+2] = f.z * scale; qr[d+3] = f.w * scale;
        }
    }

    float m = -1e30f, l = 0.f;
    float acc[DHH];
    #pragma unroll
    for (int d = 0; d < DHH; d++) acc[d] = 0.f;

    for (int kt = 0; kt < SS; kt += KT) {
        const float* kp = k + ((size_t)(b * SS + kt + t)) * DD + h * DHH;
        const float* vp = v + ((size_t)(b * SS + kt + t)) * DD + h * DHH;
        #pragma unroll
        for (int d = 0; d < DHH; d += 4) {
            *(float4*)&Ks[t][d] = *(const float4*)(kp + d);
            *(float4*)&Vs[t][d] = *(const float4*)(vp + d);
        }
        __syncthreads();

        #pragma unroll 2
        for (int j = 0; j < KT; j++) {
            float s0 = 0.f, s1 = 0.f, s2 = 0.f, s3 = 0.f;
            #pragma unroll
            for (int d = 0; d < DHH; d += 4) {
                float4 kf = *(const float4*)&Ks[j][d];
                s0 = fmaf(qr[d],   kf.x, s0);
                s1 = fmaf(qr[d+1], kf.y, s1);
                s2 = fmaf(qr[d+2], kf.z, s2);
                s3 = fmaf(qr[d+3], kf.w, s3);
            }
            float s = (s0 + s1) + (s2 + s3);
            if (s > m) {
                float c = __expf(m - s);
                m = s;
                l *= c;
                #pragma unroll
                for (int d = 0; d < DHH; d++) acc[d] *= c;
            }
            float p = __expf(s - m);
            l += p;
            #pragma unroll
            for (int d = 0; d < DHH; d += 4) {
                float4 vf = *(const float4*)&Vs[j][d];
                acc[d]   = fmaf(p, vf.x, acc[d]);
                acc[d+1] = fmaf(p, vf.y, acc[d+1]);
                acc[d+2] = fmaf(p, vf.z, acc[d+2]);
                acc[d+3] = fmaf(p, vf.w, acc[d+3]);
            }
        }
        __syncthreads();
    }

    float inv_l = 1.0f / l;
    float* op = o + (size_t)row * DD + h * DHH;
    #pragma unroll
    for (int d = 0; d < DHH; d += 4) {
        float4 f;
        f.x = acc[d] * inv_l; f.y = acc[d+1] * inv_l;
        f.z = acc[d+2] * inv_l; f.w = acc[d+3] * inv_l;
        *(float4*)(op + d) = f;
    }
}

// ---------------- launch --------------------------------------------------
extern "C" void kernel_launch(void* const* d_in, const int* in_sizes, int n_in,
                              void* d_out, int out_size)
{
    const float* x     = (const float*)d_in[0];
    const float* Wq    = (const float*)d_in[1];
    const float* Wk    = (const float*)d_in[2];
    const float* Wv    = (const float*)d_in[3];
    const float* Wo    = (const float*)d_in[4];
    const float* ln1_g = (const float*)d_in[5];
    const float* ln1_b = (const float*)d_in[6];
    const float* ln2_g = (const float*)d_in[7];
    const float* ln2_b = (const float*)d_in[8];
    const float* W2    = (const float*)d_in[9];
    const float* b2    = (const float*)d_in[10];
    const float* W3    = (const float*)d_in[11];
    const float* b3    = (const float*)d_in[12];
    float* out = (float*)d_out;

    float *xn, *qb, *kb, *vb, *attn, *res, *hid;
    cudaGetSymbolAddress((void**)&xn,   g_xn);
    cudaGetSymbolAddress((void**)&qb,   g_q);
    cudaGetSymbolAddress((void**)&kb,   g_k);
    cudaGetSymbolAddress((void**)&vb,   g_v);
    cudaGetSymbolAddress((void**)&attn, g_attn);
    cudaGetSymbolAddress((void**)&res,  g_res);
    cudaGetSymbolAddress((void**)&hid,  g_hid);

    // 1. LN1
    ln_kernel<<<MM, 256>>>(x, ln1_g, ln1_b, xn);

    // 2. QKV projections
    dim3 g_qkv(DD / 64, MM / 64);
    gemm_kernel<0><<<g_qkv, 256>>>(xn, Wq, nullptr, nullptr, qb, MM, DD, DD);
    gemm_kernel<0><<<g_qkv, 256>>>(xn, Wk, nullptr, nullptr, kb, MM, DD, DD);
    gemm_kernel<0><<<g_qkv, 256>>>(xn, Wv, nullptr, nullptr, vb, MM, DD, DD);

    // 3. RoPE on q, k
    int rope_n = MM * HH * (DHH / 2);
    rope_kernel<<<(rope_n + 255) / 256, 256>>>(qb, kb);

    // 4. Attention
    dim3 g_attn_grid(SS / 128, HH, BB);
    attn_kernel<<<g_attn_grid, 128>>>(qb, kb, vb, attn);

    // 5. Output projection + residual:  res = attn @ Wo^T + x
    gemm_kernel<2><<<g_qkv, 256>>>(attn, Wo, nullptr, x, res, MM, DD, DD);

    // 6. LN2
    ln_kernel<<<MM, 256>>>(res, ln2_g, ln2_b, xn);

    // 7. MLP up + GELU:  hid = gelu(xn @ W2^T + b2)
    dim3 g_mlp1(DMM / 64, MM / 64);
    gemm_kernel<1><<<g_mlp1, 256>>>(xn, W2, b2, nullptr, hid, MM, DMM, DD);

    // 8. MLP down + bias + residual: out = hid @ W3^T + b3 + res
    dim3 g_mlp2(DD / 64, MM / 64);
    gemm_kernel<2><<<g_mlp2, 256>>>(hid, W3, b3, res, out, MM, DD, DMM);
}

// round 3
// speedup vs baseline: 2.1368x; 2.1368x over previous
#include <cuda_runtime.h>
#include <cuda_bf16.h>
#include <math.h>
#include <stdint.h>

// Problem constants
#define BB 2
#define SS 4096
#define DD 256
#define HH 8
#define DHH 32
#define DMM 1024
#define MM (BB*SS)   // 8192

// ---------------- scratch (device globals, allocation-free) ----------------
__device__ float g_xn  [MM*DD];
__device__ float g_q   [MM*DD];
__device__ float g_k   [MM*DD];
__device__ float g_v   [MM*DD];
__device__ float g_attn[MM*DD];
__device__ float g_res [MM*DD];
__device__ float g_hid [MM*DMM];

// ---------------- LayerNorm ----------------
__global__ void ln_kernel(const float* __restrict__ x,
                          const float* __restrict__ g,
                          const float* __restrict__ b,
                          float* __restrict__ out)
{
    int row = blockIdx.x;
    int tid = threadIdx.x;
    const float* xr = x + (size_t)row * DD;
    float v = xr[tid];
    float s = v, s2 = v * v;
    #pragma unroll
    for (int off = 16; off > 0; off >>= 1) {
        s  += __shfl_down_sync(0xffffffffu, s,  off);
        s2 += __shfl_down_sync(0xffffffffu, s2, off);
    }
    __shared__ float ws[8], ws2[8];
    __shared__ float s_mu, s_rstd;
    int wid = tid >> 5, lane = tid & 31;
    if (lane == 0) { ws[wid] = s; ws2[wid] = s2; }
    __syncthreads();
    if (tid == 0) {
        float ts = 0.f, ts2 = 0.f;
        #pragma unroll
        for (int i = 0; i < 8; i++) { ts += ws[i]; ts2 += ws2[i]; }
        float mu = ts * (1.0f / DD);
        float var = ts2 * (1.0f / DD) - mu * mu;
        s_mu = mu;
        s_rstd = rsqrtf(var + 1e-5f);
    }
    __syncthreads();
    out[(size_t)row * DD + tid] = (v - s_mu) * s_rstd * g[tid] + b[tid];
}

// ---------------- Generic SGEMM: C[M,N] = A[M,K] @ W[N,K]^T (+epilogue) ----
template<int EPI>
__global__ void __launch_bounds__(256)
gemm_kernel(const float* __restrict__ A, const float* __restrict__ W,
            const float* __restrict__ bias, const float* __restrict__ res,
            float* __restrict__ C, int M, int N, int K)
{
    __shared__ float As[16][64];
    __shared__ float Bs[16][64];

    int t  = threadIdx.x;
    int tx = t & 15;
    int ty = t >> 4;
    int rm0 = blockIdx.y * 64;
    int cn0 = blockIdx.x * 64;

    int lrow = t >> 2;
    int lc4  = (t & 3) * 4;

    float acc[4][4];
    #pragma unroll
    for (int i = 0; i < 4; i++)
        #pragma unroll
        for (int j = 0; j < 4; j++) acc[i][j] = 0.f;

    for (int k0 = 0; k0 < K; k0 += 16) {
        float4 a4 = *(const float4*)(A + (size_t)(rm0 + lrow) * K + k0 + lc4);
        float4 w4 = *(const float4*)(W + (size_t)(cn0 + lrow) * K + k0 + lc4);
        As[lc4 + 0][lrow] = a4.x; As[lc4 + 1][lrow] = a4.y;
        As[lc4 + 2][lrow] = a4.z; As[lc4 + 3][lrow] = a4.w;
        Bs[lc4 + 0][lrow] = w4.x; Bs[lc4 + 1][lrow] = w4.y;
        Bs[lc4 + 2][lrow] = w4.z; Bs[lc4 + 3][lrow] = w4.w;
        __syncthreads();
        #pragma unroll
        for (int kk = 0; kk < 16; kk++) {
            float4 af = *(const float4*)(&As[kk][ty * 4]);
            float4 bf = *(const float4*)(&Bs[kk][tx * 4]);
            float a[4] = {af.x, af.y, af.z, af.w};
            float b[4] = {bf.x, bf.y, bf.z, bf.w};
            #pragma unroll
            for (int i = 0; i < 4; i++)
                #pragma unroll
                for (int j = 0; j < 4; j++)
                    acc[i][j] = fmaf(a[i], b[j], acc[i][j]);
        }
        __syncthreads();
    }

    #pragma unroll
    for (int i = 0; i < 4; i++) {
        int r = rm0 + ty * 4 + i;
        #pragma unroll
        for (int j = 0; j < 4; j++) {
            int c = cn0 + tx * 4 + j;
            float v = acc[i][j];
            if (EPI == 1) {
                v += bias[c];
                v = 0.5f * v * (1.0f + erff(v * 0.70710678118654752f));
            } else if (EPI == 2) {
                if (bias) v += bias[c];
                v += res[(size_t)r * N + c];
            }
            C[(size_t)r * N + c] = v;
        }
    }
}

// ---------------- RoPE ----------------
__global__ void rope_kernel(float* __restrict__ q, float* __restrict__ k)
{
    int idx = blockIdx.x * blockDim.x + threadIdx.x;
    if (idx >= MM * HH * (DHH / 2)) return;
    int i   = idx & 15;
    int h   = (idx >> 4) & 7;
    int row = idx >> 7;
    int pos = row & (SS - 1);

    float inv = __expf(-((float)(2 * i) / 32.0f) * 9.210340371976184f);
    float theta = (float)pos * inv;
    float sn, cs;
    sincosf(theta, &sn, &cs);

    size_t off = (size_t)row * DD + h * DHH + 2 * i;
    float q0 = q[off], q1 = q[off + 1];
    q[off]     = q0 * cs - q1 * sn;
    q[off + 1] = q1 * cs + q0 * sn;
    float k0 = k[off], k1 = k[off + 1];
    k[off]     = k0 * cs - k1 * sn;
    k[off + 1] = k1 * cs + k0 * sn;
}

// ======================= Tensor-core flash attention ========================
// bf16x2 split precision (hi+lo): every product computed as
// hi*hi + hi*lo + lo*hi  -> effective ~2^-17 relative error.
#define QT  128
#define KTT 64
#define KSP 40   // bf16 row stride: conflict-free for LDS pairs and ldmatrix
#define L2E 1.4426950408889634f

__device__ __forceinline__ uint32_t smem_u32(const void* p) {
    return (uint32_t)__cvta_generic_to_shared(p);
}
__device__ __forceinline__ uint32_t pack_bf16f(float a, float b) {
    __nv_bfloat162 t = __floats2bfloat162_rn(a, b);
    return *reinterpret_cast<uint32_t*>(&t);
}
__device__ __forceinline__ float bf16_hi(float x) {
    return __bfloat162float(__float2bfloat16_rn(x));
}
__device__ __forceinline__ void split_store(__nv_bfloat16* hi, __nv_bfloat16* lo,
                                            float a, float b) {
    float ha = bf16_hi(a), hb = bf16_hi(b);
    *reinterpret_cast<uint32_t*>(hi) = pack_bf16f(ha, hb);
    *reinterpret_cast<uint32_t*>(lo) = pack_bf16f(a - ha, b - hb);
}
__device__ __forceinline__ void mma16816(float* c, const uint32_t* a,
                                         uint32_t b0, uint32_t b1) {
    asm volatile(
        "mma.sync.aligned.m16n8k16.row.col.f32.bf16.bf16.f32 "
        "{%0,%1,%2,%3}, {%4,%5,%6,%7}, {%8,%9}, {%0,%1,%2,%3};"
        : "+f"(c[0]), "+f"(c[1]), "+f"(c[2]), "+f"(c[3])
        : "r"(a[0]), "r"(a[1]), "r"(a[2]), "r"(a[3]), "r"(b0), "r"(b1));
}
__device__ __forceinline__ void ldsm_x4_t(uint32_t& r0, uint32_t& r1,
                                          uint32_t& r2, uint32_t& r3, uint32_t addr) {
    asm volatile(
        "ldmatrix.sync.aligned.m8n8.x4.trans.shared.b16 {%0,%1,%2,%3}, [%4];"
        : "=r"(r0), "=r"(r1), "=r"(r2), "=r"(r3) : "r"(addr));
}

// grid = (S/QT, H, B), block = 256 (8 warps, 16 query rows each)
__global__ void __launch_bounds__(256)
attn_mma_kernel(const float* __restrict__ q, const float* __restrict__ k,
                const float* __restrict__ v, float* __restrict__ o)
{
    __shared__ float Qs[QT][DHH];
    __shared__ __nv_bfloat16 Khi[KTT][KSP];
    __shared__ __nv_bfloat16 Klo[KTT][KSP];
    __shared__ __nv_bfloat16 Vhi[KTT][KSP];
    __shared__ __nv_bfloat16 Vlo[KTT][KSP];

    const int b = blockIdx.z, h = blockIdx.y;
    const int tid = threadIdx.x;
    const int w = tid >> 5, lane = tid & 31;
    const int qbase = blockIdx.x * QT;
    const int gr = lane >> 2;        // row within 8-row group
    const int gc = (lane & 3) * 2;   // col pair base

    // ---- stage Q tile
    {
        int row = tid >> 1;
        int c0 = (tid & 1) * 16;
        const float4* src = (const float4*)(q + ((size_t)(b * SS + qbase + row)) * DD + h * DHH + c0);
        float4* dst = (float4*)&Qs[row][c0];
        dst[0] = src[0]; dst[1] = src[1]; dst[2] = src[2]; dst[3] = src[3];
    }
    __syncthreads();

    // ---- Q fragments (scaled, split hi/lo), resident for whole kernel
    const float scale = 0.17677669529663687f;  // 1/sqrt(32)
    uint32_t qh[2][4], ql[2][4];
    #pragma unroll
    for (int s = 0; s < 2; s++) {
        #pragma unroll
        for (int i = 0; i < 4; i++) {
            int rr = w * 16 + gr + (i & 1) * 8;
            int dd = s * 16 + gc + (i >> 1) * 8;
            float x0 = Qs[rr][dd]     * scale;
            float x1 = Qs[rr][dd + 1] * scale;
            float h0 = bf16_hi(x0), h1 = bf16_hi(x1);
            qh[s][i] = pack_bf16f(h0, h1);
            ql[s][i] = pack_bf16f(x0 - h0, x1 - h1);
        }
    }

    float m0 = -1e30f, m1 = -1e30f, l0 = 0.f, l1 = 0.f;
    float of[4][4];
    #pragma unroll
    for (int i = 0; i < 4; i++)
        #pragma unroll
        for (int j = 0; j < 4; j++) of[i][j] = 0.f;

    for (int kt = 0; kt < SS; kt += KTT) {
        __syncthreads();
        // ---- fill K/V tiles (split to bf16 hi/lo)
        {
            int row = tid >> 2;
            int f4  = tid & 3;
            const float* kp = k + ((size_t)(b * SS + kt + row)) * DD + h * DHH;
            const float* vp = v + ((size_t)(b * SS + kt + row)) * DD + h * DHH;
            #pragma unroll
            for (int half = 0; half < 2; half++) {
                int d0 = f4 * 4 + half * 16;
                float4 kf = *(const float4*)(kp + d0);
                split_store(&Khi[row][d0],     &Klo[row][d0],     kf.x, kf.y);
                split_store(&Khi[row][d0 + 2], &Klo[row][d0 + 2], kf.z, kf.w);
                float4 vf = *(const float4*)(vp + d0);
                split_store(&Vhi[row][d0],     &Vlo[row][d0],     vf.x, vf.y);
                split_store(&Vhi[row][d0 + 2], &Vlo[row][d0 + 2], vf.z, vf.w);
            }
        }
        __syncthreads();

        // ---- S = Q K^T (64 keys), 8 n-tiles x 2 k-slabs x 3 split-MMAs
        float sf[8][4];
        #pragma unroll
        for (int t = 0; t < 8; t++) { sf[t][0] = 0; sf[t][1] = 0; sf[t][2] = 0; sf[t][3] = 0; }

        #pragma unroll
        for (int s = 0; s < 2; s++) {
            #pragma unroll
            for (int nt = 0; nt < 8; nt++) {
                int krow = nt * 8 + gr;
                int dd = s * 16 + gc;
                uint32_t bh0 = *(const uint32_t*)&Khi[krow][dd];
                uint32_t bh1 = *(const uint32_t*)&Khi[krow][dd + 8];
                uint32_t bl0 = *(const uint32_t*)&Klo[krow][dd];
                uint32_t bl1 = *(const uint32_t*)&Klo[krow][dd + 8];
                mma16816(sf[nt], qh[s], bh0, bh1);
                mma16816(sf[nt], qh[s], bl0, bl1);
                mma16816(sf[nt], ql[s], bh0, bh1);
            }
        }

        // ---- online softmax (rows gr and gr+8 of this warp's 16)
        float mx0 = -1e30f, mx1 = -1e30f;
        #pragma unroll
        for (int t = 0; t < 8; t++) {
            mx0 = fmaxf(mx0, fmaxf(sf[t][0], sf[t][1]));
            mx1 = fmaxf(mx1, fmaxf(sf[t][2], sf[t][3]));
        }
        mx0 = fmaxf(mx0, __shfl_xor_sync(0xffffffffu, mx0, 1));
        mx0 = fmaxf(mx0, __shfl_xor_sync(0xffffffffu, mx0, 2));
        mx1 = fmaxf(mx1, __shfl_xor_sync(0xffffffffu, mx1, 1));
        mx1 = fmaxf(mx1, __shfl_xor_sync(0xffffffffu, mx1, 2));
        float mn0 = fmaxf(m0, mx0), mn1 = fmaxf(m1, mx1);
        float al0 = exp2f((m0 - mn0) * L2E), al1 = exp2f((m1 - mn1) * L2E);
        m0 = mn0; m1 = mn1;
        float rs0 = 0.f, rs1 = 0.f;
        #pragma unroll
        for (int t = 0; t < 8; t++) {
            sf[t][0] = exp2f((sf[t][0] - m0) * L2E);
            sf[t][1] = exp2f((sf[t][1] - m0) * L2E);
            sf[t][2] = exp2f((sf[t][2] - m1) * L2E);
            sf[t][3] = exp2f((sf[t][3] - m1) * L2E);
            rs0 += sf[t][0] + sf[t][1];
            rs1 += sf[t][2] + sf[t][3];
        }
        rs0 += __shfl_xor_sync(0xffffffffu, rs0, 1);
        rs0 += __shfl_xor_sync(0xffffffffu, rs0, 2);
        rs1 += __shfl_xor_sync(0xffffffffu, rs1, 1);
        rs1 += __shfl_xor_sync(0xffffffffu, rs1, 2);
        l0 = l0 * al0 + rs0;
        l1 = l1 * al1 + rs1;
        #pragma unroll
        for (int dt = 0; dt < 4; dt++) {
            of[dt][0] *= al0; of[dt][1] *= al0; of[dt][2] *= al1; of[dt][3] *= al1;
        }

        // ---- O += P V  (P stays in registers: C-frag -> A-frag identity)
        #pragma unroll
        for (int ks = 0; ks < 4; ks++) {
            uint32_t pah[4], pal[4];
            #pragma unroll
            for (int half = 0; half < 2; half++) {
                float p0 = sf[2 * ks + half][0], p1 = sf[2 * ks + half][1];
                float p2 = sf[2 * ks + half][2], p3 = sf[2 * ks + half][3];
                float h0 = bf16_hi(p0), h1 = bf16_hi(p1);
                float h2 = bf16_hi(p2), h3 = bf16_hi(p3);
                pah[half * 2 + 0] = pack_bf16f(h0, h1);
                pah[half * 2 + 1] = pack_bf16f(h2, h3);
                pal[half * 2 + 0] = pack_bf16f(p0 - h0, p1 - h1);
                pal[half * 2 + 1] = pack_bf16f(p2 - h2, p3 - h3);
            }
            #pragma unroll
            for (int dp = 0; dp < 2; dp++) {
                uint32_t vh0, vh1, vh2, vh3, vl0, vl1, vl2, vl3;
                uint32_t ah = smem_u32(&Vhi[ks * 16 + (lane & 15)][dp * 16 + ((lane >> 4) << 3)]);
                uint32_t al = smem_u32(&Vlo[ks * 16 + (lane & 15)][dp * 16 + ((lane >> 4) << 3)]);
                ldsm_x4_t(vh0, vh1, vh2, vh3, ah);
                ldsm_x4_t(vl0, vl1, vl2, vl3, al);
                mma16816(of[2 * dp],     pah, vh0, vh1);
                mma16816(of[2 * dp],     pah, vl0, vl1);
                mma16816(of[2 * dp],     pal, vh0, vh1);
                mma16816(of[2 * dp + 1], pah, vh2, vh3);
                mma16816(of[2 * dp + 1], pah, vl2, vl3);
                mma16816(of[2 * dp + 1], pal, vh2, vh3);
            }
        }
    }

    // ---- normalize + write
    float il0 = 1.f / l0, il1 = 1.f / l1;
    int row0 = b * SS + qbase + w * 16 + gr;
    #pragma unroll
    for (int dt = 0; dt < 4; dt++) {
        int col = h * DHH + dt * 8 + gc;
        float2 v0 = make_float2(of[dt][0] * il0, of[dt][1] * il0);
        float2 v1 = make_float2(of[dt][2] * il1, of[dt][3] * il1);
        *(float2*)(o + (size_t)row0 * DD + col) = v0;
        *(float2*)(o + (size_t)(row0 + 8) * DD + col) = v1;
    }
}

// ---------------- launch --------------------------------------------------
extern "C" void kernel_launch(void* const* d_in, const int* in_sizes, int n_in,
                              void* d_out, int out_size)
{
    const float* x     = (const float*)d_in[0];
    const float* Wq    = (const float*)d_in[1];
    const float* Wk    = (const float*)d_in[2];
    const float* Wv    = (const float*)d_in[3];
    const float* Wo    = (const float*)d_in[4];
    const float* ln1_g = (const float*)d_in[5];
    const float* ln1_b = (const float*)d_in[6];
    const float* ln2_g = (const float*)d_in[7];
    const float* ln2_b = (const float*)d_in[8];
    const float* W2    = (const float*)d_in[9];
    const float* b2    = (const float*)d_in[10];
    const float* W3    = (const float*)d_in[11];
    const float* b3    = (const float*)d_in[12];
    float* out = (float*)d_out;

    float *xn, *qb, *kb, *vb, *attn, *res, *hid;
    cudaGetSymbolAddress((void**)&xn,   g_xn);
    cudaGetSymbolAddress((void**)&qb,   g_q);
    cudaGetSymbolAddress((void**)&kb,   g_k);
    cudaGetSymbolAddress((void**)&vb,   g_v);
    cudaGetSymbolAddress((void**)&attn, g_attn);
    cudaGetSymbolAddress((void**)&res,  g_res);
    cudaGetSymbolAddress((void**)&hid,  g_hid);

    // 1. LN1
    ln_kernel<<<MM, 256>>>(x, ln1_g, ln1_b, xn);

    // 2. QKV projections
    dim3 g_qkv(DD / 64, MM / 64);
    gemm_kernel<0><<<g_qkv, 256>>>(xn, Wq, nullptr, nullptr, qb, MM, DD, DD);
    gemm_kernel<0><<<g_qkv, 256>>>(xn, Wk, nullptr, nullptr, kb, MM, DD, DD);
    gemm_kernel<0><<<g_qkv, 256>>>(xn, Wv, nullptr, nullptr, vb, MM, DD, DD);

    // 3. RoPE
    int rope_n = MM * HH * (DHH / 2);
    rope_kernel<<<(rope_n + 255) / 256, 256>>>(qb, kb);

    // 4. Attention (tensor cores, bf16x2)
    dim3 g_attn_grid(SS / QT, HH, BB);
    attn_mma_kernel<<<g_attn_grid, 256>>>(qb, kb, vb, attn);

    // 5. Output projection + residual
    gemm_kernel<2><<<g_qkv, 256>>>(attn, Wo, nullptr, x, res, MM, DD, DD);

    // 6. LN2
    ln_kernel<<<MM, 256>>>(res, ln2_g, ln2_b, xn);

    // 7. MLP up + GELU
    dim3 g_mlp1(DMM / 64, MM / 64);
    gemm_kernel<1><<<g_mlp1, 256>>>(xn, W2, b2, nullptr, hid, MM, DMM, DD);

    // 8. MLP down + bias + residual
    dim3 g_mlp2(DD / 64, MM / 64);
    gemm_kernel<2><<<g_mlp2, 256>>>(hid, W3, b3, res, out, MM, DD, DMM);
}

// round 4
// speedup vs baseline: 2.8791x; 1.3474x over previous
#include <cuda_runtime.h>
#include <cuda_bf16.h>
#include <math.h>
#include <stdint.h>

// Problem constants
#define BB 2
#define SS 4096
#define DD 256
#define HH 8
#define DHH 32
#define DMM 1024
#define MM (BB*SS)   // 8192

// ---------------- scratch (device globals, allocation-free) ----------------
__device__ float g_xn  [MM*DD];
__device__ float g_q   [MM*DD];
__device__ float g_k   [MM*DD];
__device__ float g_v   [MM*DD];
__device__ float g_attn[MM*DD];
__device__ float g_res [MM*DD];
__device__ float g_hid [MM*DMM];

// weight hi/lo bf16 buffers
__device__ __nv_bfloat16 g_wq_h[DD*DD],  g_wq_l[DD*DD];
__device__ __nv_bfloat16 g_wk_h[DD*DD],  g_wk_l[DD*DD];
__device__ __nv_bfloat16 g_wv_h[DD*DD],  g_wv_l[DD*DD];
__device__ __nv_bfloat16 g_wo_h[DD*DD],  g_wo_l[DD*DD];
__device__ __nv_bfloat16 g_w2_h[DMM*DD], g_w2_l[DMM*DD];
__device__ __nv_bfloat16 g_w3_h[DD*DMM], g_w3_l[DD*DMM];

// ---------------- helpers ----------------
__device__ __forceinline__ uint32_t smem_u32(const void* p) {
    return (uint32_t)__cvta_generic_to_shared(p);
}
__device__ __forceinline__ uint32_t pack_bf16f(float a, float b) {
    __nv_bfloat162 t = __floats2bfloat162_rn(a, b);
    return *reinterpret_cast<uint32_t*>(&t);
}
__device__ __forceinline__ float bf16_hi(float x) {
    return __bfloat162float(__float2bfloat16_rn(x));
}
__device__ __forceinline__ void split_store(__nv_bfloat16* hi, __nv_bfloat16* lo,
                                            float a, float b) {
    float ha = bf16_hi(a), hb = bf16_hi(b);
    *reinterpret_cast<uint32_t*>(hi) = pack_bf16f(ha, hb);
    *reinterpret_cast<uint32_t*>(lo) = pack_bf16f(a - ha, b - hb);
}
__device__ __forceinline__ void mma16816(float* c, const uint32_t* a,
                                         uint32_t b0, uint32_t b1) {
    asm volatile(
        "mma.sync.aligned.m16n8k16.row.col.f32.bf16.bf16.f32 "
        "{%0,%1,%2,%3}, {%4,%5,%6,%7}, {%8,%9}, {%0,%1,%2,%3};"
        : "+f"(c[0]), "+f"(c[1]), "+f"(c[2]), "+f"(c[3])
        : "r"(a[0]), "r"(a[1]), "r"(a[2]), "r"(a[3]), "r"(b0), "r"(b1));
}
__device__ __forceinline__ void ldsm_x4_t(uint32_t& r0, uint32_t& r1,
                                          uint32_t& r2, uint32_t& r3, uint32_t addr) {
    asm volatile(
        "ldmatrix.sync.aligned.m8n8.x4.trans.shared.b16 {%0,%1,%2,%3}, [%4];"
        : "=r"(r0), "=r"(r1), "=r"(r2), "=r"(r3) : "r"(addr));
}

// ---------------- weight split conversion ----------------
__global__ void conv_kernel(const float* __restrict__ src,
                            __nv_bfloat16* __restrict__ hi,
                            __nv_bfloat16* __restrict__ lo, int n)
{
    int i = blockIdx.x * blockDim.x + threadIdx.x;
    if (i >= n) return;
    float x = src[i];
    float h = bf16_hi(x);
    hi[i] = __float2bfloat16_rn(h);
    lo[i] = __float2bfloat16_rn(x - h);
}

// ---------------- LayerNorm ----------------
__global__ void ln_kernel(const float* __restrict__ x,
                          const float* __restrict__ g,
                          const float* __restrict__ b,
                          float* __restrict__ out)
{
    int row = blockIdx.x;
    int tid = threadIdx.x;
    const float* xr = x + (size_t)row * DD;
    float v = xr[tid];
    float s = v, s2 = v * v;
    #pragma unroll
    for (int off = 16; off > 0; off >>= 1) {
        s  += __shfl_down_sync(0xffffffffu, s,  off);
        s2 += __shfl_down_sync(0xffffffffu, s2, off);
    }
    __shared__ float ws[8], ws2[8];
    __shared__ float s_mu, s_rstd;
    int wid = tid >> 5, lane = tid & 31;
    if (lane == 0) { ws[wid] = s; ws2[wid] = s2; }
    __syncthreads();
    if (tid == 0) {
        float ts = 0.f, ts2 = 0.f;
        #pragma unroll
        for (int i = 0; i < 8; i++) { ts += ws[i]; ts2 += ws2[i]; }
        float mu = ts * (1.0f / DD);
        float var = ts2 * (1.0f / DD) - mu * mu;
        s_mu = mu;
        s_rstd = rsqrtf(var + 1e-5f);
    }
    __syncthreads();
    out[(size_t)row * DD + tid] = (v - s_mu) * s_rstd * g[tid] + b[tid];
}

// ================= Tensor-core GEMM: C[M,N] = A[M,K] @ W[N,K]^T =============
// A fp32 split to bf16 hi/lo in smem; W pre-split in global.
// 3 split-MMAs per product: hi*hi + hi*lo + lo*hi.
// EPI: 0 = none, 1 = bias + exact GELU, 2 = bias(optional) + residual add
#define GBM 128
#define GBN 64
#define GBK 32
#define GKP 40

template<int EPI>
__global__ void __launch_bounds__(256)
gemm_mma_kernel(const float* __restrict__ A,
                const __nv_bfloat16* __restrict__ Whi,
                const __nv_bfloat16* __restrict__ Wlo,
                const float* __restrict__ bias, const float* __restrict__ res,
                float* __restrict__ C, int M, int N, int K)
{
    __shared__ __nv_bfloat16 Ahi[GBM][GKP];
    __shared__ __nv_bfloat16 Alo[GBM][GKP];
    __shared__ __nv_bfloat16 Bhi[GBN][GKP];
    __shared__ __nv_bfloat16 Blo[GBN][GKP];

    const int tid  = threadIdx.x;
    const int w    = tid >> 5, lane = tid & 31;
    const int wm   = w >> 1, wn = w & 1;            // 4x2 warps
    const int gr   = lane >> 2;
    const int gc   = (lane & 3) * 2;
    const int rm0  = blockIdx.y * GBM;
    const int cn0  = blockIdx.x * GBN;

    const int arow = tid >> 1;
    const int acol = (tid & 1) * 16;
    const int brow = tid >> 2;
    const int bcol = (tid & 3) * 8;

    float acc[2][4][4];
    #pragma unroll
    for (int mt = 0; mt < 2; mt++)
        #pragma unroll
        for (int nt = 0; nt < 4; nt++)
            #pragma unroll
            for (int i = 0; i < 4; i++) acc[mt][nt][i] = 0.f;

    for (int k0 = 0; k0 < K; k0 += GBK) {
        // stage A (fp32 -> split bf16)
        {
            const float* ap = A + (size_t)(rm0 + arow) * K + k0 + acol;
            #pragma unroll
            for (int c = 0; c < 16; c += 4) {
                float4 f = *(const float4*)(ap + c);
                split_store(&Ahi[arow][acol + c],     &Alo[arow][acol + c],     f.x, f.y);
                split_store(&Ahi[arow][acol + c + 2], &Alo[arow][acol + c + 2], f.z, f.w);
            }
        }
        // stage B (pre-split bf16 copy)
        {
            const uint4* bh = (const uint4*)(Whi + (size_t)(cn0 + brow) * K + k0 + bcol);
            const uint4* bl = (const uint4*)(Wlo + (size_t)(cn0 + brow) * K + k0 + bcol);
            *(uint4*)&Bhi[brow][bcol] = *bh;
            *(uint4*)&Blo[brow][bcol] = *bl;
        }
        __syncthreads();

        #pragma unroll
        for (int s = 0; s < 2; s++) {
            uint32_t ah[2][4], al[2][4];
            #pragma unroll
            for (int mt = 0; mt < 2; mt++) {
                int r = wm * 32 + mt * 16 + gr;
                int c = s * 16 + gc;
                ah[mt][0] = *(const uint32_t*)&Ahi[r][c];
                ah[mt][1] = *(const uint32_t*)&Ahi[r + 8][c];
                ah[mt][2] = *(const uint32_t*)&Ahi[r][c + 8];
                ah[mt][3] = *(const uint32_t*)&Ahi[r + 8][c + 8];
                al[mt][0] = *(const uint32_t*)&Alo[r][c];
                al[mt][1] = *(const uint32_t*)&Alo[r + 8][c];
                al[mt][2] = *(const uint32_t*)&Alo[r][c + 8];
                al[mt][3] = *(const uint32_t*)&Alo[r + 8][c + 8];
            }
            #pragma unroll
            for (int nt = 0; nt < 4; nt++) {
                int n = wn * 32 + nt * 8 + gr;
                int c = s * 16 + gc;
                uint32_t bh0 = *(const uint32_t*)&Bhi[n][c];
                uint32_t bh1 = *(const uint32_t*)&Bhi[n][c + 8];
                uint32_t bl0 = *(const uint32_t*)&Blo[n][c];
                uint32_t bl1 = *(const uint32_t*)&Blo[n][c + 8];
                #pragma unroll
                for (int mt = 0; mt < 2; mt++) {
                    mma16816(acc[mt][nt], ah[mt], bh0, bh1);
                    mma16816(acc[mt][nt], ah[mt], bl0, bl1);
                    mma16816(acc[mt][nt], al[mt], bh0, bh1);
                }
            }
        }
        __syncthreads();
    }

    // epilogue
    #pragma unroll
    for (int mt = 0; mt < 2; mt++) {
        #pragma unroll
        for (int half = 0; half < 2; half++) {
            int r = rm0 + wm * 32 + mt * 16 + gr + half * 8;
            #pragma unroll
            for (int nt = 0; nt < 4; nt++) {
                int cidx = cn0 + wn * 32 + nt * 8 + gc;
                float v0 = acc[mt][nt][half * 2 + 0];
                float v1 = acc[mt][nt][half * 2 + 1];
                if (EPI == 1) {
                    v0 += bias[cidx];
                    v1 += bias[cidx + 1];
                    v0 = 0.5f * v0 * (1.0f + erff(v0 * 0.70710678118654752f));
                    v1 = 0.5f * v1 * (1.0f + erff(v1 * 0.70710678118654752f));
                } else if (EPI == 2) {
                    if (bias) { v0 += bias[cidx]; v1 += bias[cidx + 1]; }
                    v0 += res[(size_t)r * N + cidx];
                    v1 += res[(size_t)r * N + cidx + 1];
                }
                *(float2*)(C + (size_t)r * N + cidx) = make_float2(v0, v1);
            }
        }
    }
}

// ---------------- RoPE ----------------
__global__ void rope_kernel(float* __restrict__ q, float* __restrict__ k)
{
    int idx = blockIdx.x * blockDim.x + threadIdx.x;
    if (idx >= MM * HH * (DHH / 2)) return;
    int i   = idx & 15;
    int h   = (idx >> 4) & 7;
    int row = idx >> 7;
    int pos = row & (SS - 1);

    float inv = __expf(-((float)(2 * i) / 32.0f) * 9.210340371976184f);
    float theta = (float)pos * inv;
    float sn, cs;
    sincosf(theta, &sn, &cs);

    size_t off = (size_t)row * DD + h * DHH + 2 * i;
    float q0 = q[off], q1 = q[off + 1];
    q[off]     = q0 * cs - q1 * sn;
    q[off + 1] = q1 * cs + q0 * sn;
    float k0 = k[off], k1 = k[off + 1];
    k[off]     = k0 * cs - k1 * sn;
    k[off + 1] = k1 * cs + k0 * sn;
}

// ======================= Tensor-core flash attention ========================
#define QT  128
#define KTT 64
#define KSP 40
#define L2E 1.4426950408889634f

// grid = (S/QT, H, B), block = 256 (8 warps, 16 query rows each)
__global__ void __launch_bounds__(256)
attn_mma_kernel(const float* __restrict__ q, const float* __restrict__ k,
                const float* __restrict__ v, float* __restrict__ o)
{
    __shared__ float Qs[QT][DHH];
    __shared__ __nv_bfloat16 Khi[KTT][KSP];
    __shared__ __nv_bfloat16 Klo[KTT][KSP];
    __shared__ __nv_bfloat16 Vhi[KTT][KSP];
    __shared__ __nv_bfloat16 Vlo[KTT][KSP];

    const int b = blockIdx.z, h = blockIdx.y;
    const int tid = threadIdx.x;
    const int w = tid >> 5, lane = tid & 31;
    const int qbase = blockIdx.x * QT;
    const int gr = lane >> 2;
    const int gc = (lane & 3) * 2;

    {
        int row = tid >> 1;
        int c0 = (tid & 1) * 16;
        const float4* src = (const float4*)(q + ((size_t)(b * SS + qbase + row)) * DD + h * DHH + c0);
        float4* dst = (float4*)&Qs[row][c0];
        dst[0] = src[0]; dst[1] = src[1]; dst[2] = src[2]; dst[3] = src[3];
    }
    __syncthreads();

    const float scale = 0.17677669529663687f;
    uint32_t qh[2][4], ql[2][4];
    #pragma unroll
    for (int s = 0; s < 2; s++) {
        #pragma unroll
        for (int i = 0; i < 4; i++) {
            int rr = w * 16 + gr + (i & 1) * 8;
            int dd = s * 16 + gc + (i >> 1) * 8;
            float x0 = Qs[rr][dd]     * scale;
            float x1 = Qs[rr][dd + 1] * scale;
            float h0 = bf16_hi(x0), h1 = bf16_hi(x1);
            qh[s][i] = pack_bf16f(h0, h1);
            ql[s][i] = pack_bf16f(x0 - h0, x1 - h1);
        }
    }

    float m0 = -1e30f, m1 = -1e30f, l0 = 0.f, l1 = 0.f;
    float of[4][4];
    #pragma unroll
    for (int i = 0; i < 4; i++)
        #pragma unroll
        for (int j = 0; j < 4; j++) of[i][j] = 0.f;

    for (int kt = 0; kt < SS; kt += KTT) {
        __syncthreads();
        {
            int row = tid >> 2;
            int f4  = tid & 3;
            const float* kp = k + ((size_t)(b * SS + kt + row)) * DD + h * DHH;
            const float* vp = v + ((size_t)(b * SS + kt + row)) * DD + h * DHH;
            #pragma unroll
            for (int half = 0; half < 2; half++) {
                int d0 = f4 * 4 + half * 16;
                float4 kf = *(const float4*)(kp + d0);
                split_store(&Khi[row][d0],     &Klo[row][d0],     kf.x, kf.y);
                split_store(&Khi[row][d0 + 2], &Klo[row][d0 + 2], kf.z, kf.w);
                float4 vf = *(const float4*)(vp + d0);
                split_store(&Vhi[row][d0],     &Vlo[row][d0],     vf.x, vf.y);
                split_store(&Vhi[row][d0 + 2], &Vlo[row][d0 + 2], vf.z, vf.w);
            }
        }
        __syncthreads();

        float sf[8][4];
        #pragma unroll
        for (int t = 0; t < 8; t++) { sf[t][0] = 0; sf[t][1] = 0; sf[t][2] = 0; sf[t][3] = 0; }

        #pragma unroll
        for (int s = 0; s < 2; s++) {
            #pragma unroll
            for (int nt = 0; nt < 8; nt++) {
                int krow = nt * 8 + gr;
                int dd = s * 16 + gc;
                uint32_t bh0 = *(const uint32_t*)&Khi[krow][dd];
                uint32_t bh1 = *(const uint32_t*)&Khi[krow][dd + 8];
                uint32_t bl0 = *(const uint32_t*)&Klo[krow][dd];
                uint32_t bl1 = *(const uint32_t*)&Klo[krow][dd + 8];
                mma16816(sf[nt], qh[s], bh0, bh1);
                mma16816(sf[nt], qh[s], bl0, bl1);
                mma16816(sf[nt], ql[s], bh0, bh1);
            }
        }

        float mx0 = -1e30f, mx1 = -1e30f;
        #pragma unroll
        for (int t = 0; t < 8; t++) {
            mx0 = fmaxf(mx0, fmaxf(sf[t][0], sf[t][1]));
            mx1 = fmaxf(mx1, fmaxf(sf[t][2], sf[t][3]));
        }
        mx0 = fmaxf(mx0, __shfl_xor_sync(0xffffffffu, mx0, 1));
        mx0 = fmaxf(mx0, __shfl_xor_sync(0xffffffffu, mx0, 2));
        mx1 = fmaxf(mx1, __shfl_xor_sync(0xffffffffu, mx1, 1));
        mx1 = fmaxf(mx1, __shfl_xor_sync(0xffffffffu, mx1, 2));
        float mn0 = fmaxf(m0, mx0), mn1 = fmaxf(m1, mx1);
        float al0 = exp2f((m0 - mn0) * L2E), al1 = exp2f((m1 - mn1) * L2E);
        m0 = mn0; m1 = mn1;
        float rs0 = 0.f, rs1 = 0.f;
        #pragma unroll
        for (int t = 0; t < 8; t++) {
            sf[t][0] = exp2f((sf[t][0] - m0) * L2E);
            sf[t][1] = exp2f((sf[t][1] - m0) * L2E);
            sf[t][2] = exp2f((sf[t][2] - m1) * L2E);
            sf[t][3] = exp2f((sf[t][3] - m1) * L2E);
            rs0 += sf[t][0] + sf[t][1];
            rs1 += sf[t][2] + sf[t][3];
        }
        rs0 += __shfl_xor_sync(0xffffffffu, rs0, 1);
        rs0 += __shfl_xor_sync(0xffffffffu, rs0, 2);
        rs1 += __shfl_xor_sync(0xffffffffu, rs1, 1);
        rs1 += __shfl_xor_sync(0xffffffffu, rs1, 2);
        l0 = l0 * al0 + rs0;
        l1 = l1 * al1 + rs1;
        #pragma unroll
        for (int dt = 0; dt < 4; dt++) {
            of[dt][0] *= al0; of[dt][1] *= al0; of[dt][2] *= al1; of[dt][3] *= al1;
        }

        #pragma unroll
        for (int ks = 0; ks < 4; ks++) {
            uint32_t pah[4], pal[4];
            #pragma unroll
            for (int half = 0; half < 2; half++) {
                float p0 = sf[2 * ks + half][0], p1 = sf[2 * ks + half][1];
                float p2 = sf[2 * ks + half][2], p3 = sf[2 * ks + half][3];
                float h0 = bf16_hi(p0), h1 = bf16_hi(p1);
                float h2 = bf16_hi(p2), h3 = bf16_hi(p3);
                pah[half * 2 + 0] = pack_bf16f(h0, h1);
                pah[half * 2 + 1] = pack_bf16f(h2, h3);
                pal[half * 2 + 0] = pack_bf16f(p0 - h0, p1 - h1);
                pal[half * 2 + 1] = pack_bf16f(p2 - h2, p3 - h3);
            }
            #pragma unroll
            for (int dp = 0; dp < 2; dp++) {
                uint32_t vh0, vh1, vh2, vh3, vl0, vl1, vl2, vl3;
                uint32_t ah = smem_u32(&Vhi[ks * 16 + (lane & 15)][dp * 16 + ((lane >> 4) << 3)]);
                uint32_t al = smem_u32(&Vlo[ks * 16 + (lane & 15)][dp * 16 + ((lane >> 4) << 3)]);
                ldsm_x4_t(vh0, vh1, vh2, vh3, ah);
                ldsm_x4_t(vl0, vl1, vl2, vl3, al);
                mma16816(of[2 * dp],     pah, vh0, vh1);
                mma16816(of[2 * dp],     pah, vl0, vl1);
                mma16816(of[2 * dp],     pal, vh0, vh1);
                mma16816(of[2 * dp + 1], pah, vh2, vh3);
                mma16816(of[2 * dp + 1], pah, vl2, vl3);
                mma16816(of[2 * dp + 1], pal, vh2, vh3);
            }
        }
    }

    float il0 = 1.f / l0, il1 = 1.f / l1;
    int row0 = b * SS + qbase + w * 16 + gr;
    #pragma unroll
    for (int dt = 0; dt < 4; dt++) {
        int col = h * DHH + dt * 8 + gc;
        float2 v0 = make_float2(of[dt][0] * il0, of[dt][1] * il0);
        float2 v1 = make_float2(of[dt][2] * il1, of[dt][3] * il1);
        *(float2*)(o + (size_t)row0 * DD + col) = v0;
        *(float2*)(o + (size_t)(row0 + 8) * DD + col) = v1;
    }
}

// ---------------- launch --------------------------------------------------
extern "C" void kernel_launch(void* const* d_in, const int* in_sizes, int n_in,
                              void* d_out, int out_size)
{
    const float* x     = (const float*)d_in[0];
    const float* Wq    = (const float*)d_in[1];
    const float* Wk    = (const float*)d_in[2];
    const float* Wv    = (const float*)d_in[3];
    const float* Wo    = (const float*)d_in[4];
    const float* ln1_g = (const float*)d_in[5];
    const float* ln1_b = (const float*)d_in[6];
    const float* ln2_g = (const float*)d_in[7];
    const float* ln2_b = (const float*)d_in[8];
    const float* W2    = (const float*)d_in[9];
    const float* b2    = (const float*)d_in[10];
    const float* W3    = (const float*)d_in[11];
    const float* b3    = (const float*)d_in[12];
    float* out = (float*)d_out;

    float *xn, *qb, *kb, *vb, *attn, *res, *hid;
    cudaGetSymbolAddress((void**)&xn,   g_xn);
    cudaGetSymbolAddress((void**)&qb,   g_q);
    cudaGetSymbolAddress((void**)&kb,   g_k);
    cudaGetSymbolAddress((void**)&vb,   g_v);
    cudaGetSymbolAddress((void**)&attn, g_attn);
    cudaGetSymbolAddress((void**)&res,  g_res);
    cudaGetSymbolAddress((void**)&hid,  g_hid);

    __nv_bfloat16 *wqh, *wql, *wkh, *wkl, *wvh, *wvl, *woh, *wol, *w2h, *w2l, *w3h, *w3l;
    cudaGetSymbolAddress((void**)&wqh, g_wq_h); cudaGetSymbolAddress((void**)&wql, g_wq_l);
    cudaGetSymbolAddress((void**)&wkh, g_wk_h); cudaGetSymbolAddress((void**)&wkl, g_wk_l);
    cudaGetSymbolAddress((void**)&wvh, g_wv_h); cudaGetSymbolAddress((void**)&wvl, g_wv_l);
    cudaGetSymbolAddress((void**)&woh, g_wo_h); cudaGetSymbolAddress((void**)&wol, g_wo_l);
    cudaGetSymbolAddress((void**)&w2h, g_w2_h); cudaGetSymbolAddress((void**)&w2l, g_w2_l);
    cudaGetSymbolAddress((void**)&w3h, g_w3_h); cudaGetSymbolAddress((void**)&w3l, g_w3_l);

    // 0. split weights to bf16 hi/lo
    conv_kernel<<<(DD*DD + 255) / 256, 256>>>(Wq, wqh, wql, DD*DD);
    conv_kernel<<<(DD*DD + 255) / 256, 256>>>(Wk, wkh, wkl, DD*DD);
    conv_kernel<<<(DD*DD + 255) / 256, 256>>>(Wv, wvh, wvl, DD*DD);
    conv_kernel<<<(DD*DD + 255) / 256, 256>>>(Wo, woh, wol, DD*DD);
    conv_kernel<<<(DMM*DD + 255) / 256, 256>>>(W2, w2h, w2l, DMM*DD);
    conv_kernel<<<(DD*DMM + 255) / 256, 256>>>(W3, w3h, w3l, DD*DMM);

    // 1. LN1
    ln_kernel<<<MM, 256>>>(x, ln1_g, ln1_b, xn);

    // 2. QKV projections (tensor cores)
    dim3 g_qkv(DD / GBN, MM / GBM);
    gemm_mma_kernel<0><<<g_qkv, 256>>>(xn, wqh, wql, nullptr, nullptr, qb, MM, DD, DD);
    gemm_mma_kernel<0><<<g_qkv, 256>>>(xn, wkh, wkl, nullptr, nullptr, kb, MM, DD, DD);
    gemm_mma_kernel<0><<<g_qkv, 256>>>(xn, wvh, wvl, nullptr, nullptr, vb, MM, DD, DD);

    // 3. RoPE
    int rope_n = MM * HH * (DHH / 2);
    rope_kernel<<<(rope_n + 255) / 256, 256>>>(qb, kb);

    // 4. Attention (tensor cores)
    dim3 g_attn_grid(SS / QT, HH, BB);
    attn_mma_kernel<<<g_attn_grid, 256>>>(qb, kb, vb, attn);

    // 5. Output projection + residual
    gemm_mma_kernel<2><<<g_qkv, 256>>>(attn, woh, wol, nullptr, x, res, MM, DD, DD);

    // 6. LN2
    ln_kernel<<<MM, 256>>>(res, ln2_g, ln2_b, xn);

    // 7. MLP up + GELU
    dim3 g_mlp1(DMM / GBN, MM / GBM);
    gemm_mma_kernel<1><<<g_mlp1, 256>>>(xn, w2h, w2l, b2, nullptr, hid, MM, DMM, DD);

    // 8. MLP down + bias + residual
    dim3 g_mlp2(DD / GBN, MM / GBM);
    gemm_mma_kernel<2><<<g_mlp2, 256>>>(hid, w3h, w3l, b3, res, out, MM, DD, DMM);
}